// round 16
// baseline (speedup 1.0000x reference)
#include <cuda_runtime.h>
#include <cuda_bf16.h>

// Problem constants
#define BB   2
#define SS   1024
#define DIMM 1024
#define NH   16
#define HD   64
#define BS   (BB * SS)
#define NEG_INF_F (-1000000000.0f)

// ---------------------------------------------------------------------------
// Scratch (static device globals; no allocation anywhere)
// ---------------------------------------------------------------------------
__device__ float g_q [BS * DIMM];
__device__ float g_k [BS * DIMM];
__device__ __nv_bfloat16 g_xhi [BS * DIMM];
__device__ __nv_bfloat16 g_xlo [BS * DIMM];
__device__ __nv_bfloat16 g_aohi[BS * DIMM];
__device__ __nv_bfloat16 g_aolo[BS * DIMM];
__device__ __nv_bfloat16 g_whi [4 * DIMM * DIMM];  // transposed [n][k]
__device__ __nv_bfloat16 g_wlo [4 * DIMM * DIMM];
__device__ __nv_bfloat16 g_qhi [BS * DIMM];
__device__ __nv_bfloat16 g_qlo [BS * DIMM];
__device__ __nv_bfloat16 g_khi [BS * DIMM];
__device__ __nv_bfloat16 g_klo [BS * DIMM];
__device__ __nv_bfloat16 g_vhi [BS * DIMM];
__device__ __nv_bfloat16 g_vlo [BS * DIMM];

// ---------------------------------------------------------------------------
// PTX helpers
// ---------------------------------------------------------------------------
__device__ __forceinline__ unsigned smem_u32(const void* p) {
    unsigned a;
    asm("{ .reg .u64 t; cvta.to.shared.u64 t, %1; cvt.u32.u64 %0, t; }"
        : "=r"(a) : "l"(p));
    return a;
}

__device__ __forceinline__ void cp_async16(unsigned saddr, const void* gaddr) {
    asm volatile("cp.async.cg.shared.global [%0], [%1], 16;"
                 :: "r"(saddr), "l"(gaddr));
}
#define CP_COMMIT() asm volatile("cp.async.commit_group;")
template <int N>
__device__ __forceinline__ void cp_wait() {
    asm volatile("cp.async.wait_group %0;" :: "n"(N));
}

__device__ __forceinline__ void ldm_x4(unsigned addr, unsigned* r) {
    asm volatile("ldmatrix.sync.aligned.m8n8.x4.shared.b16 {%0,%1,%2,%3}, [%4];"
                 : "=r"(r[0]), "=r"(r[1]), "=r"(r[2]), "=r"(r[3]) : "r"(addr));
}

__device__ __forceinline__ void ldm_x4_t(unsigned addr, unsigned* r) {
    asm volatile("ldmatrix.sync.aligned.m8n8.x4.trans.shared.b16 {%0,%1,%2,%3}, [%4];"
                 : "=r"(r[0]), "=r"(r[1]), "=r"(r[2]), "=r"(r[3]) : "r"(addr));
}

__device__ __forceinline__ void mma_bf16(float* c, const unsigned* a,
                                         const unsigned* b) {
    asm volatile(
        "mma.sync.aligned.m16n8k16.row.col.f32.bf16.bf16.f32 "
        "{%0,%1,%2,%3}, {%4,%5,%6,%7}, {%8,%9}, {%0,%1,%2,%3};"
        : "+f"(c[0]), "+f"(c[1]), "+f"(c[2]), "+f"(c[3])
        : "r"(a[0]), "r"(a[1]), "r"(a[2]), "r"(a[3]), "r"(b[0]), "r"(b[1]));
}

__device__ __forceinline__ unsigned pk2(float x, float y) {
    __nv_bfloat162 t = __floats2bfloat162_rn(x, y);
    return *(unsigned*)&t;
}

__device__ __forceinline__ void split2(float x, float y, unsigned& hw, unsigned& lw) {
    hw = pk2(x, y);
    __nv_bfloat162* hp = (__nv_bfloat162*)&hw;
    lw = pk2(x - __bfloat162float(hp->x), y - __bfloat162float(hp->y));
}

// ---------------------------------------------------------------------------
// Weight prep (all 4 weights, one launch)
// ---------------------------------------------------------------------------
__global__ __launch_bounds__(256) void prep_w4(const float* __restrict__ w0,
                                               const float* __restrict__ w1,
                                               const float* __restrict__ w2,
                                               const float* __restrict__ w3,
                                               __nv_bfloat16* __restrict__ hi,
                                               __nv_bfloat16* __restrict__ lo)
{
    __shared__ float t[32][33];
    const int z = blockIdx.z;
    const float* w = (z == 0) ? w0 : (z == 1) ? w1 : (z == 2) ? w2 : w3;
    hi += (size_t)z * DIMM * DIMM;
    lo += (size_t)z * DIMM * DIMM;

    const int tx = threadIdx.x & 31, ty = threadIdx.x >> 5;
    const int n0 = blockIdx.x * 32, k0 = blockIdx.y * 32;
#pragma unroll
    for (int i = 0; i < 4; i++)
        t[ty + 8 * i][tx] = w[(size_t)(k0 + ty + 8 * i) * DIMM + n0 + tx];
    __syncthreads();
#pragma unroll
    for (int i = 0; i < 4; i++) {
        float v = t[tx][ty + 8 * i];
        __nv_bfloat16 h = __float2bfloat16_rn(v);
        float r = v - __bfloat162float(h);
        size_t o = (size_t)(n0 + ty + 8 * i) * DIMM + k0 + tx;
        hi[o] = h;
        lo[o] = __float2bfloat16_rn(r);
    }
}

// ---------------------------------------------------------------------------
// Activation split: fp32 -> bf16 hi/lo (x only)
// ---------------------------------------------------------------------------
__global__ __launch_bounds__(256) void split_f32(const float4* __restrict__ in,
                                                 __nv_bfloat16* __restrict__ hi,
                                                 __nv_bfloat16* __restrict__ lo)
{
    const int i = blockIdx.x * 256 + threadIdx.x;
    float4 v = in[i];
    unsigned hw0, lw0, hw1, lw1;
    split2(v.x, v.y, hw0, lw0);
    split2(v.z, v.w, hw1, lw1);
    ((uint2*)hi)[i] = make_uint2(hw0, hw1);
    ((uint2*)lo)[i] = make_uint2(lw0, lw1);
}

// ---------------------------------------------------------------------------
// MMA GEMM core: 128x128 tile, BK=64, 3-stage, single sync (R12 proven).
// ---------------------------------------------------------------------------
#define BK        64
#define ROW_ELEMS 72
#define ROW_BYTES (ROW_ELEMS * 2)       // 144
#define TILE_B    (128 * ROW_BYTES)     // 18432
#define STAGE_B   (4 * TILE_B)          // 73728
#define NSTAGE    3
#define GEMM_SMEM (NSTAGE * STAGE_B)    // 221184
#define GT        512

template <int MODE>
__device__ __forceinline__ void gemm_body(
    const __nv_bfloat16* __restrict__ Ahi, const __nv_bfloat16* __restrict__ Alo,
    const __nv_bfloat16* __restrict__ Bhi, const __nv_bfloat16* __restrict__ Blo,
    float* __restrict__ C, __nv_bfloat16* __restrict__ Chi,
    __nv_bfloat16* __restrict__ Clo,
    int M, int N, int K, int row0, int col0)
{
    extern __shared__ char smem[];
    const unsigned sb = smem_u32(smem);

    const int tid  = threadIdx.x;
    const int lane = tid & 31;
    const int wid  = tid >> 5;
    const int wm   = wid & 3;
    const int wn   = wid >> 2;

    const int t0r = tid >> 3, t0s = tid & 7;
    const int t1r = t0r + 64;
    const size_t gA0 = (size_t)(row0 + t0r) * K + t0s * 8;
    const size_t gA1 = (size_t)(row0 + t1r) * K + t0s * 8;
    const size_t gB0 = (size_t)(col0 + t0r) * K + t0s * 8;
    const size_t gB1 = (size_t)(col0 + t1r) * K + t0s * 8;
    const unsigned s0 = t0r * ROW_BYTES + t0s * 16;
    const unsigned s1 = t1r * ROW_BYTES + t0s * 16;

#define LOAD_CHUNK(c, stg) do {                                              \
    const int kk = (c) * BK;                                                 \
    unsigned base = sb + (stg) * STAGE_B;                                    \
    cp_async16(base + 0 * TILE_B + s0, Ahi + gA0 + kk);                      \
    cp_async16(base + 0 * TILE_B + s1, Ahi + gA1 + kk);                      \
    cp_async16(base + 1 * TILE_B + s0, Alo + gA0 + kk);                      \
    cp_async16(base + 1 * TILE_B + s1, Alo + gA1 + kk);                      \
    cp_async16(base + 2 * TILE_B + s0, Bhi + gB0 + kk);                      \
    cp_async16(base + 2 * TILE_B + s1, Bhi + gB1 + kk);                      \
    cp_async16(base + 3 * TILE_B + s0, Blo + gB0 + kk);                      \
    cp_async16(base + 3 * TILE_B + s1, Blo + gB1 + kk);                      \
} while (0)

    float acc[2][4][4];
#pragma unroll
    for (int i = 0; i < 2; i++)
#pragma unroll
        for (int j = 0; j < 4; j++)
#pragma unroll
            for (int q = 0; q < 4; q++) acc[i][j][q] = 0.0f;

    const int l7 = lane & 7, m4 = lane >> 3;
    const unsigned aoff = (wm * 32 + (m4 & 1) * 8 + l7) * ROW_BYTES + (m4 >> 1) * 16;
    const unsigned boff = (wn * 32 + ((m4 & 2) ? 8 : 0) + l7) * ROW_BYTES + (m4 & 1) * 16;

    const int NCH = K / BK;   // 16

    LOAD_CHUNK(0, 0); CP_COMMIT();
    LOAD_CHUNK(1, 1); CP_COMMIT();

    for (int c = 0; c < NCH; c++) {
        cp_wait<1>();
        __syncthreads();

        if (c + 2 < NCH) LOAD_CHUNK(c + 2, (c + 2) % NSTAGE);
        CP_COMMIT();

        const unsigned stg = sb + (c % NSTAGE) * STAGE_B;
#pragma unroll
        for (int ks = 0; ks < 4; ks++) {
            const unsigned kb = ks * 32;
            unsigned ah[2][4], al[2][4], bh[2][4], bl[2][4];
#pragma unroll
            for (int mi = 0; mi < 2; mi++) {
                unsigned ad = stg + aoff + mi * (16 * ROW_BYTES) + kb;
                ldm_x4(ad + 0 * TILE_B, ah[mi]);
                ldm_x4(ad + 1 * TILE_B, al[mi]);
            }
#pragma unroll
            for (int ng = 0; ng < 2; ng++) {
                unsigned bd = stg + boff + ng * (16 * ROW_BYTES) + kb;
                ldm_x4(bd + 2 * TILE_B, bh[ng]);
                ldm_x4(bd + 3 * TILE_B, bl[ng]);
            }
#pragma unroll
            for (int mi = 0; mi < 2; mi++)
#pragma unroll
                for (int ni = 0; ni < 4; ni++) {
                    const int ng = ni >> 1, half = (ni & 1) * 2;
                    unsigned bhr[2] = { bh[ng][half], bh[ng][half + 1] };
                    unsigned blr[2] = { bl[ng][half], bl[ng][half + 1] };
                    mma_bf16(acc[mi][ni], ah[mi], bhr);
                    mma_bf16(acc[mi][ni], ah[mi], blr);
                    mma_bf16(acc[mi][ni], al[mi], bhr);
                }
        }
    }

    const int erow = row0 + wm * 32 + (lane >> 2);
    const int ecol = col0 + wn * 32 + (lane & 3) * 2;
#pragma unroll
    for (int mi = 0; mi < 2; mi++)
#pragma unroll
        for (int ni = 0; ni < 4; ni++) {
            const size_t o0 = (size_t)(erow + mi * 16) * N + ecol + ni * 8;
            const size_t o1 = o0 + (size_t)8 * N;
            if (MODE == 0) {
                C[o0] = acc[mi][ni][0]; C[o0 + 1] = acc[mi][ni][1];
                C[o1] = acc[mi][ni][2]; C[o1 + 1] = acc[mi][ni][3];
            } else {
                unsigned h0, l0w, h1, l1w;
                split2(acc[mi][ni][0], acc[mi][ni][1], h0, l0w);
                split2(acc[mi][ni][2], acc[mi][ni][3], h1, l1w);
                *(unsigned*)(Chi + o0) = h0;
                *(unsigned*)(Clo + o0) = l0w;
                *(unsigned*)(Chi + o1) = h1;
                *(unsigned*)(Clo + o1) = l1w;
            }
        }
#undef LOAD_CHUNK
}

__global__ __launch_bounds__(GT) void gemm_mma(
    const __nv_bfloat16* __restrict__ Ahi, const __nv_bfloat16* __restrict__ Alo,
    const __nv_bfloat16* __restrict__ Bhi, const __nv_bfloat16* __restrict__ Blo,
    float* __restrict__ C, int M, int N, int K)
{
    gemm_body<0>(Ahi, Alo, Bhi, Blo, C, nullptr, nullptr, M, N, K,
                 blockIdx.y * 128, blockIdx.x * 128);
}

__global__ __launch_bounds__(GT) void gemm_qkv(
    const __nv_bfloat16* __restrict__ Ahi, const __nv_bfloat16* __restrict__ Alo,
    const __nv_bfloat16* __restrict__ Whi, const __nv_bfloat16* __restrict__ Wlo,
    float* __restrict__ Cq, float* __restrict__ Ck,
    __nv_bfloat16* __restrict__ Vhi, __nv_bfloat16* __restrict__ Vlo)
{
    const size_t WSZ = (size_t)DIMM * DIMM;
    const int z = blockIdx.z;
    const __nv_bfloat16* Bhi = Whi + (size_t)z * WSZ;
    const __nv_bfloat16* Blo = Wlo + (size_t)z * WSZ;
    if (z == 2) {
        gemm_body<1>(Ahi, Alo, Bhi, Blo, nullptr, Vhi, Vlo, BS, DIMM, DIMM,
                     blockIdx.y * 128, blockIdx.x * 128);
    } else {
        float* C = (z == 0) ? Cq : Ck;
        gemm_body<0>(Ahi, Alo, Bhi, Blo, C, nullptr, nullptr, BS, DIMM, DIMM,
                     blockIdx.y * 128, blockIdx.x * 128);
    }
}

// ---------------------------------------------------------------------------
// RoPE: reads fp32 q/k, writes split bf16 hi/lo directly.
// ---------------------------------------------------------------------------
#define ROT(xx, yy, c, s) { float _t = (xx)*(c) - (yy)*(s); (yy) = (xx)*(s) + (yy)*(c); (xx) = _t; }

__global__ __launch_bounds__(256) void rope_split(const float* __restrict__ q,
                                                  const float* __restrict__ k,
                                                  const int* __restrict__ Hm,
                                                  const int* __restrict__ Bm,
                                                  const float* __restrict__ fc,
                                                  const float* __restrict__ fs,
                                                  __nv_bfloat16* __restrict__ qhi,
                                                  __nv_bfloat16* __restrict__ qlo,
                                                  __nv_bfloat16* __restrict__ khi,
                                                  __nv_bfloat16* __restrict__ klo)
{
    const int tok = blockIdx.x;
    const int tid = threadIdx.x;
    const int h = tid >> 4;
    const int m = tid & 15;
    const int base = tok * DIMM + h * HD;

    float2 qab = *(const float2*)&q[base + 2 * m];
    float2 qcd = *(const float2*)&q[base + 2 * m + 32];
    float2 kab = *(const float2*)&k[base + 2 * m];
    float2 kcd = *(const float2*)&k[base + 2 * m + 32];

    const float cH0 = fc[32 + m],      sH0 = fs[32 + m];
    const float cH1 = fc[32 + m + 16], sH1 = fs[32 + m + 16];
    const float cB0a = fc[32 + 2 * m],     sB0a = fs[32 + 2 * m];
    const float cB0b = fc[32 + 2 * m + 1], sB0b = fs[32 + 2 * m + 1];
    const float cB1a = fc[64 + 2 * m],     sB1a = fs[64 + 2 * m];
    const float cB1b = fc[64 + 2 * m + 1], sB1b = fs[64 + 2 * m + 1];

#pragma unroll
    for (int i = 0; i < 6; i++) {
        if (Hm[i * BS + tok]) {
            ROT(qab.x, qab.y, cH0, sH0); ROT(qcd.x, qcd.y, cH1, sH1);
            ROT(kab.x, kab.y, cH0, sH0); ROT(kcd.x, kcd.y, cH1, sH1);
        }
        if (Bm[(i * 2 + 0) * BS + tok]) {
            ROT(qab.x, qcd.x, cB0a, sB0a); ROT(qab.y, qcd.y, cB0b, sB0b);
            ROT(kab.x, kcd.x, cB0a, sB0a); ROT(kab.y, kcd.y, cB0b, sB0b);
        }
        if (Bm[(i * 2 + 1) * BS + tok]) {
            ROT(qab.x, qcd.x, cB1a, sB1a); ROT(qab.y, qcd.y, cB1b, sB1b);
            ROT(kab.x, kcd.x, cB1a, sB1a); ROT(kab.y, kcd.y, cB1b, sB1b);
        }
    }

    unsigned hw, lw;
    split2(qab.x, qab.y, hw, lw);
    *(unsigned*)(qhi + base + 2 * m) = hw;  *(unsigned*)(qlo + base + 2 * m) = lw;
    split2(qcd.x, qcd.y, hw, lw);
    *(unsigned*)(qhi + base + 2 * m + 32) = hw;  *(unsigned*)(qlo + base + 2 * m + 32) = lw;
    split2(kab.x, kab.y, hw, lw);
    *(unsigned*)(khi + base + 2 * m) = hw;  *(unsigned*)(klo + base + 2 * m) = lw;
    split2(kcd.x, kcd.y, hw, lw);
    *(unsigned*)(khi + base + 2 * m + 32) = hw;  *(unsigned*)(klo + base + 2 * m + 32) = lw;
}

// ---------------------------------------------------------------------------
// Flash attention (R10-proven split-k version): q-tile 64, kv-tile 64,
// 256 threads, 2 CTAs/SM. 8 warps = 4 q-groups (16 rows) x 2 k-halves
// (32 cols). Per-warp online (m,l,O) over disjoint k-subsequence; one
// split-k merge via smem at the end.
// ---------------------------------------------------------------------------
#define FROWB   144
#define FQTILE  (64 * FROWB)            // 9216 per q plane
#define FKTILE  (64 * FROWB)            // 9216 per kv plane
#define FSTAGE  (4 * FKTILE)            // 36864
#define FLASH_SMEM (2 * FQTILE + 2 * FSTAGE)   // 92160

__global__ __launch_bounds__(256, 2) void flash_mma(
    const __nv_bfloat16* __restrict__ qhi, const __nv_bfloat16* __restrict__ qlo,
    const __nv_bfloat16* __restrict__ khi, const __nv_bfloat16* __restrict__ klo,
    const __nv_bfloat16* __restrict__ vhi, const __nv_bfloat16* __restrict__ vlo,
    const int* __restrict__ masks,
    __nv_bfloat16* __restrict__ aohi, __nv_bfloat16* __restrict__ aolo)
{
    extern __shared__ char smem[];
    const unsigned sb = smem_u32(smem);
    const int tid = threadIdx.x, lane = tid & 31, wid = tid >> 5;
    const int wq = wid & 3, wk = wid >> 2;
    const int bh = blockIdx.y, b = bh >> 4, h = bh & 15;
    const int q0 = blockIdx.x * 64;

    const unsigned sQh = sb, sQl = sb + FQTILE;
    const unsigned sKV = sb + 2 * FQTILE;

#pragma unroll
    for (int t = 0; t < 2; t++) {
        int seg = tid + t * 256, row = seg >> 3, s = seg & 7;
        size_t g = (size_t)(b * SS + q0 + row) * DIMM + h * HD + s * 8;
        unsigned sa = row * FROWB + s * 16;
        cp_async16(sQh + sa, qhi + g);
        cp_async16(sQl + sa, qlo + g);
    }

#define KV_LOAD(kt, stg) do {                                                \
    unsigned base = sKV + (stg) * FSTAGE;                                    \
    _Pragma("unroll")                                                        \
    for (int t = 0; t < 2; t++) {                                            \
        int seg = tid + t * 256, row = seg >> 3, s = seg & 7;                \
        size_t g = (size_t)(b * SS + (kt) * 64 + row) * DIMM + h * HD + s * 8; \
        unsigned sa = row * FROWB + s * 16;                                  \
        cp_async16(base + sa,              khi + g);                         \
        cp_async16(base + FKTILE + sa,     klo + g);                         \
        cp_async16(base + 2 * FKTILE + sa, vhi + g);                         \
        cp_async16(base + 3 * FKTILE + sa, vlo + g);                         \
    }                                                                        \
} while (0)

    KV_LOAD(0, 0); CP_COMMIT();
    KV_LOAD(1, 1); CP_COMMIT();

    float m0 = -1e30f, m1 = -1e30f, l0 = 0.0f, l1 = 0.0f;
    float acc_o[8][4];
#pragma unroll
    for (int j = 0; j < 8; j++)
#pragma unroll
        for (int q = 0; q < 4; q++) acc_o[j][q] = 0.0f;

    const int l7 = lane & 7, m4 = lane >> 3;
    const unsigned qoff = (wq * 16 + (m4 & 1) * 8 + l7) * FROWB + (m4 >> 1) * 16;
    const unsigned koff = (wk * 32 + ((m4 & 2) ? 8 : 0) + l7) * FROWB + (m4 & 1) * 16;
    const unsigned voff = (lane & 15) * FROWB + (lane >> 4) * 16;

    const int gr0 = q0 + wq * 16 + (lane >> 2);
    const int* mrow0 = masks + (size_t)b * SS * SS + (size_t)gr0 * SS;
    const int* mrow1 = mrow0 + 8 * SS;

    for (int kt = 0; kt < 16; kt++) {
        if (kt == 15) cp_wait<0>(); else cp_wait<1>();
        __syncthreads();
        const unsigned kbase = sKV + (kt & 1) * FSTAGE;

        float s[4][4];
#pragma unroll
        for (int ni = 0; ni < 4; ni++)
#pragma unroll
            for (int q = 0; q < 4; q++) s[ni][q] = 0.0f;

#pragma unroll
        for (int ks = 0; ks < 4; ks++) {
            unsigned ah[4], al[4];
            ldm_x4(sQh + qoff + ks * 32, ah);
            ldm_x4(sQl + qoff + ks * 32, al);
#pragma unroll
            for (int g = 0; g < 2; g++) {
                unsigned bh4[4], bl4[4];
                unsigned ba = kbase + koff + g * (16 * FROWB) + ks * 32;
                ldm_x4(ba, bh4);
                ldm_x4(ba + FKTILE, bl4);
                unsigned bh0[2] = { bh4[0], bh4[1] }, bh1[2] = { bh4[2], bh4[3] };
                unsigned bl0[2] = { bl4[0], bl4[1] }, bl1[2] = { bl4[2], bl4[3] };
                mma_bf16(s[2 * g],     ah, bh0); mma_bf16(s[2 * g],     ah, bl0); mma_bf16(s[2 * g],     al, bh0);
                mma_bf16(s[2 * g + 1], ah, bh1); mma_bf16(s[2 * g + 1], ah, bl1); mma_bf16(s[2 * g + 1], al, bh1);
            }
        }

        const int kc0 = kt * 64 + wk * 32 + (lane & 3) * 2;
#pragma unroll
        for (int ni = 0; ni < 4; ni++) {
            int2 mk0 = *(const int2*)(mrow0 + kc0 + ni * 8);
            int2 mk1 = *(const int2*)(mrow1 + kc0 + ni * 8);
            s[ni][0] = mk0.x ? s[ni][0] * 0.125f : NEG_INF_F;
            s[ni][1] = mk0.y ? s[ni][1] * 0.125f : NEG_INF_F;
            s[ni][2] = mk1.x ? s[ni][2] * 0.125f : NEG_INF_F;
            s[ni][3] = mk1.y ? s[ni][3] * 0.125f : NEG_INF_F;
        }

        float mx0 = -1e30f, mx1 = -1e30f;
#pragma unroll
        for (int ni = 0; ni < 4; ni++) {
            mx0 = fmaxf(mx0, fmaxf(s[ni][0], s[ni][1]));
            mx1 = fmaxf(mx1, fmaxf(s[ni][2], s[ni][3]));
        }
        mx0 = fmaxf(mx0, __shfl_xor_sync(0xffffffffu, mx0, 1));
        mx0 = fmaxf(mx0, __shfl_xor_sync(0xffffffffu, mx0, 2));
        mx1 = fmaxf(mx1, __shfl_xor_sync(0xffffffffu, mx1, 1));
        mx1 = fmaxf(mx1, __shfl_xor_sync(0xffffffffu, mx1, 2));

        float mn0 = fmaxf(m0, mx0), mn1 = fmaxf(m1, mx1);
        float al0 = __expf(m0 - mn0), al1 = __expf(m1 - mn1);
        m0 = mn0; m1 = mn1;

        float sum0 = 0.0f, sum1 = 0.0f;
#pragma unroll
        for (int ni = 0; ni < 4; ni++) {
            s[ni][0] = __expf(s[ni][0] - mn0);
            s[ni][1] = __expf(s[ni][1] - mn0);
            s[ni][2] = __expf(s[ni][2] - mn1);
            s[ni][3] = __expf(s[ni][3] - mn1);
            sum0 += s[ni][0] + s[ni][1];
            sum1 += s[ni][2] + s[ni][3];
        }
        sum0 += __shfl_xor_sync(0xffffffffu, sum0, 1);
        sum0 += __shfl_xor_sync(0xffffffffu, sum0, 2);
        sum1 += __shfl_xor_sync(0xffffffffu, sum1, 1);
        sum1 += __shfl_xor_sync(0xffffffffu, sum1, 2);
        l0 = l0 * al0 + sum0;
        l1 = l1 * al1 + sum1;

#pragma unroll
        for (int j = 0; j < 8; j++) {
            acc_o[j][0] *= al0; acc_o[j][1] *= al0;
            acc_o[j][2] *= al1; acc_o[j][3] *= al1;
        }

#pragma unroll
        for (int kc = 0; kc < 2; kc++) {
            unsigned aH[4], aL[4];
            split2(s[2 * kc][0],     s[2 * kc][1],     aH[0], aL[0]);
            split2(s[2 * kc][2],     s[2 * kc][3],     aH[1], aL[1]);
            split2(s[2 * kc + 1][0], s[2 * kc + 1][1], aH[2], aL[2]);
            split2(s[2 * kc + 1][2], s[2 * kc + 1][3], aH[3], aL[3]);
            const unsigned vrow = (wk * 32 + kc * 16) * FROWB;
#pragma unroll
            for (int dg = 0; dg < 4; dg++) {
                unsigned bh4[4], bl4[4];
                unsigned va = kbase + 2 * FKTILE + vrow + voff + dg * 32;
                ldm_x4_t(va, bh4);
                ldm_x4_t(va + FKTILE, bl4);
                unsigned b0h[2] = { bh4[0], bh4[1] }, b1h[2] = { bh4[2], bh4[3] };
                unsigned b0l[2] = { bl4[0], bl4[1] }, b1l[2] = { bl4[2], bl4[3] };
                mma_bf16(acc_o[2 * dg],     aH, b0h);
                mma_bf16(acc_o[2 * dg],     aH, b0l);
                mma_bf16(acc_o[2 * dg],     aL, b0h);
                mma_bf16(acc_o[2 * dg + 1], aH, b1h);
                mma_bf16(acc_o[2 * dg + 1], aH, b1l);
                mma_bf16(acc_o[2 * dg + 1], aL, b1h);
            }
        }

        __syncthreads();
        if (kt + 2 < 16) { KV_LOAD(kt + 2, kt & 1); CP_COMMIT(); }
    }

    // split-k merge
    float* ms = (float*)smem;
    __syncthreads();
    if (wk == 1) {
        const int r0 = lane >> 2;
        float* base0 = ms + (wq * 16 + r0) * 66;
        float* base1 = ms + (wq * 16 + r0 + 8) * 66;
        const int c = (lane & 3) * 2;
#pragma unroll
        for (int j = 0; j < 8; j++) {
            base0[c + j * 8] = acc_o[j][0]; base0[c + j * 8 + 1] = acc_o[j][1];
            base1[c + j * 8] = acc_o[j][2]; base1[c + j * 8 + 1] = acc_o[j][3];
        }
        if ((lane & 3) == 0) {
            base0[64] = m0; base0[65] = l0;
            base1[64] = m1; base1[65] = l1;
        }
    }
    __syncthreads();
    if (wk == 0) {
        const int r0 = lane >> 2;
        const float* base0 = ms + (wq * 16 + r0) * 66;
        const float* base1 = ms + (wq * 16 + r0 + 8) * 66;
        float pm0 = base0[64], pl0 = base0[65];
        float pm1 = base1[64], pl1 = base1[65];

        float mm0 = fmaxf(m0, pm0), mm1 = fmaxf(m1, pm1);
        float f0 = __expf(m0 - mm0), g0 = __expf(pm0 - mm0);
        float f1 = __expf(m1 - mm1), g1 = __expf(pm1 - mm1);
        float inv0 = 1.0f / (l0 * f0 + pl0 * g0);
        float inv1 = 1.0f / (l1 * f1 + pl1 * g1);

        const int c = (lane & 3) * 2;
        const size_t o0 = (size_t)(b * SS + gr0) * DIMM + h * HD + c;
        const size_t o1 = o0 + (size_t)8 * DIMM;
#pragma unroll
        for (int j = 0; j < 8; j++) {
            float v00 = (acc_o[j][0] * f0 + base0[c + j * 8]     * g0) * inv0;
            float v01 = (acc_o[j][1] * f0 + base0[c + j * 8 + 1] * g0) * inv0;
            float v10 = (acc_o[j][2] * f1 + base1[c + j * 8]     * g1) * inv1;
            float v11 = (acc_o[j][3] * f1 + base1[c + j * 8 + 1] * g1) * inv1;
            unsigned h0, w0, h1, w1;
            split2(v00, v01, h0, w0);
            split2(v10, v11, h1, w1);
            *(unsigned*)(aohi + o0 + j * 8) = h0;
            *(unsigned*)(aolo + o0 + j * 8) = w0;
            *(unsigned*)(aohi + o1 + j * 8) = h1;
            *(unsigned*)(aolo + o1 + j * 8) = w1;
        }
    }
#undef KV_LOAD
}

// ---------------------------------------------------------------------------
extern "C" void kernel_launch(void* const* d_in, const int* in_sizes, int n_in,
                              void* d_out, int out_size)
{
    const float* x     = (const float*)d_in[0];
    const int*   masks = (const int*)d_in[1];
    const int*   Hm    = (const int*)d_in[2];
    const int*   Bm    = (const int*)d_in[3];
    const float* fc    = (const float*)d_in[4];
    const float* fs    = (const float*)d_in[5];
    const float* wq    = (const float*)d_in[6];
    const float* wk    = (const float*)d_in[7];
    const float* wv    = (const float*)d_in[8];
    const float* wo    = (const float*)d_in[9];
    float* out = (float*)d_out;

    float *gq, *gk;
    __nv_bfloat16 *xhi, *xlo, *aohi, *aolo, *whi, *wlo;
    __nv_bfloat16 *qhi, *qlo, *khi, *klo, *vhi, *vlo;
    cudaGetSymbolAddress((void**)&gq,   g_q);
    cudaGetSymbolAddress((void**)&gk,   g_k);
    cudaGetSymbolAddress((void**)&xhi,  g_xhi);
    cudaGetSymbolAddress((void**)&xlo,  g_xlo);
    cudaGetSymbolAddress((void**)&aohi, g_aohi);
    cudaGetSymbolAddress((void**)&aolo, g_aolo);
    cudaGetSymbolAddress((void**)&whi,  g_whi);
    cudaGetSymbolAddress((void**)&wlo,  g_wlo);
    cudaGetSymbolAddress((void**)&qhi,  g_qhi);
    cudaGetSymbolAddress((void**)&qlo,  g_qlo);
    cudaGetSymbolAddress((void**)&khi,  g_khi);
    cudaGetSymbolAddress((void**)&klo,  g_klo);
    cudaGetSymbolAddress((void**)&vhi,  g_vhi);
    cudaGetSymbolAddress((void**)&vlo,  g_vlo);

    static bool attr_done = false;
    if (!attr_done) {
        cudaFuncSetAttribute(gemm_mma,  cudaFuncAttributeMaxDynamicSharedMemorySize, GEMM_SMEM);
        cudaFuncSetAttribute(gemm_qkv,  cudaFuncAttributeMaxDynamicSharedMemorySize, GEMM_SMEM);
        cudaFuncSetAttribute(flash_mma, cudaFuncAttributeMaxDynamicSharedMemorySize, FLASH_SMEM);
        attr_done = true;
    }

    prep_w4<<<dim3(32, 32, 4), 256>>>(wq, wk, wv, wo, whi, wlo);

    split_f32<<<BS * DIMM / 4 / 256, 256>>>((const float4*)x, xhi, xlo);

    gemm_qkv<<<dim3(DIMM / 128, BS / 128, 3), GT, GEMM_SMEM>>>(
        xhi, xlo, whi, wlo, gq, gk, vhi, vlo);

    rope_split<<<BS, 256>>>(gq, gk, Hm, Bm, fc, fs, qhi, qlo, khi, klo);

    flash_mma<<<dim3(SS / 64, BB * NH), 256, FLASH_SMEM>>>(
        qhi, qlo, khi, klo, vhi, vlo, masks, aohi, aolo);

    gemm_mma<<<dim3(DIMM / 128, BS / 128), GT, GEMM_SMEM>>>(
        aohi, aolo, whi + 3 * (size_t)DIMM * DIMM, wlo + 3 * (size_t)DIMM * DIMM,
        out, BS, DIMM, DIMM);
}

// round 17
// speedup vs baseline: 1.2478x; 1.2478x over previous
#include <cuda_runtime.h>
#include <cuda_fp16.h>

// Problem constants
#define BB   2
#define SS   1024
#define DIMM 1024
#define NH   16
#define HD   64
#define BS   (BB * SS)
#define NEG_INF_F (-1000000000.0f)

// ---------------------------------------------------------------------------
// Scratch (static device globals; no allocation anywhere)
// ---------------------------------------------------------------------------
__device__ float  g_q [BS * DIMM];
__device__ float  g_k [BS * DIMM];
__device__ __half g_xh [BS * DIMM];
__device__ __half g_aoh[BS * DIMM];
__device__ __half g_wh [4 * DIMM * DIMM];   // transposed [n][k]
__device__ __half g_qh [BS * DIMM];
__device__ __half g_kh [BS * DIMM];
__device__ __half g_vh [BS * DIMM];

// ---------------------------------------------------------------------------
// PTX helpers
// ---------------------------------------------------------------------------
__device__ __forceinline__ unsigned smem_u32(const void* p) {
    unsigned a;
    asm("{ .reg .u64 t; cvta.to.shared.u64 t, %1; cvt.u32.u64 %0, t; }"
        : "=r"(a) : "l"(p));
    return a;
}

__device__ __forceinline__ void cp_async16(unsigned saddr, const void* gaddr) {
    asm volatile("cp.async.cg.shared.global [%0], [%1], 16;"
                 :: "r"(saddr), "l"(gaddr));
}
#define CP_COMMIT() asm volatile("cp.async.commit_group;")
template <int N>
__device__ __forceinline__ void cp_wait() {
    asm volatile("cp.async.wait_group %0;" :: "n"(N));
}

__device__ __forceinline__ void ldm_x4(unsigned addr, unsigned* r) {
    asm volatile("ldmatrix.sync.aligned.m8n8.x4.shared.b16 {%0,%1,%2,%3}, [%4];"
                 : "=r"(r[0]), "=r"(r[1]), "=r"(r[2]), "=r"(r[3]) : "r"(addr));
}

__device__ __forceinline__ void ldm_x4_t(unsigned addr, unsigned* r) {
    asm volatile("ldmatrix.sync.aligned.m8n8.x4.trans.shared.b16 {%0,%1,%2,%3}, [%4];"
                 : "=r"(r[0]), "=r"(r[1]), "=r"(r[2]), "=r"(r[3]) : "r"(addr));
}

__device__ __forceinline__ void mma_f16(float* c, const unsigned* a,
                                        const unsigned* b) {
    asm volatile(
        "mma.sync.aligned.m16n8k16.row.col.f32.f16.f16.f32 "
        "{%0,%1,%2,%3}, {%4,%5,%6,%7}, {%8,%9}, {%0,%1,%2,%3};"
        : "+f"(c[0]), "+f"(c[1]), "+f"(c[2]), "+f"(c[3])
        : "r"(a[0]), "r"(a[1]), "r"(a[2]), "r"(a[3]), "r"(b[0]), "r"(b[1]));
}

__device__ __forceinline__ unsigned pkh2(float x, float y) {
    __half2 t = __floats2half2_rn(x, y);
    return *(unsigned*)&t;
}

// ---------------------------------------------------------------------------
// Weight prep (all 4 weights, one launch): fp32 w[k][n] -> fp16 [n][k]
// ---------------------------------------------------------------------------
__global__ __launch_bounds__(256) void prep_w4(const float* __restrict__ w0,
                                               const float* __restrict__ w1,
                                               const float* __restrict__ w2,
                                               const float* __restrict__ w3,
                                               __half* __restrict__ wh)
{
    __shared__ float t[32][33];
    const int z = blockIdx.z;
    const float* w = (z == 0) ? w0 : (z == 1) ? w1 : (z == 2) ? w2 : w3;
    wh += (size_t)z * DIMM * DIMM;

    const int tx = threadIdx.x & 31, ty = threadIdx.x >> 5;
    const int n0 = blockIdx.x * 32, k0 = blockIdx.y * 32;
#pragma unroll
    for (int i = 0; i < 4; i++)
        t[ty + 8 * i][tx] = w[(size_t)(k0 + ty + 8 * i) * DIMM + n0 + tx];
    __syncthreads();
#pragma unroll
    for (int i = 0; i < 4; i++) {
        float v = t[tx][ty + 8 * i];
        wh[(size_t)(n0 + ty + 8 * i) * DIMM + k0 + tx] = __float2half_rn(v);
    }
}

// ---------------------------------------------------------------------------
// Activation convert: fp32 -> fp16 (x only)
// ---------------------------------------------------------------------------
__global__ __launch_bounds__(256) void cvt_f32(const float4* __restrict__ in,
                                               __half* __restrict__ out)
{
    const int i = blockIdx.x * 256 + threadIdx.x;
    float4 v = in[i];
    ((uint2*)out)[i] = make_uint2(pkh2(v.x, v.y), pkh2(v.z, v.w));
}

// ---------------------------------------------------------------------------
// MMA GEMM core: 128x128 tile, BK=64, 3-stage, single sync (R12 loop),
// single-pass fp16. MODE 0: fp32 out. MODE 1: fp16 out.
// ---------------------------------------------------------------------------
#define BK        64
#define ROW_ELEMS 72
#define ROW_BYTES (ROW_ELEMS * 2)       // 144
#define TILE_B    (128 * ROW_BYTES)     // 18432
#define STAGE_B   (2 * TILE_B)          // 36864 (A, B)
#define NSTAGE    3
#define GEMM_SMEM (NSTAGE * STAGE_B)    // 110592
#define GT        512

template <int MODE>
__device__ __forceinline__ void gemm_body(
    const __half* __restrict__ A, const __half* __restrict__ B,
    float* __restrict__ C, __half* __restrict__ Ch,
    int M, int N, int K, int row0, int col0)
{
    extern __shared__ char smem[];
    const unsigned sb = smem_u32(smem);

    const int tid  = threadIdx.x;
    const int lane = tid & 31;
    const int wid  = tid >> 5;
    const int wm   = wid & 3;
    const int wn   = wid >> 2;

    const int t0r = tid >> 3, t0s = tid & 7;
    const int t1r = t0r + 64;
    const size_t gA0 = (size_t)(row0 + t0r) * K + t0s * 8;
    const size_t gA1 = (size_t)(row0 + t1r) * K + t0s * 8;
    const size_t gB0 = (size_t)(col0 + t0r) * K + t0s * 8;
    const size_t gB1 = (size_t)(col0 + t1r) * K + t0s * 8;
    const unsigned s0 = t0r * ROW_BYTES + t0s * 16;
    const unsigned s1 = t1r * ROW_BYTES + t0s * 16;

#define LOAD_CHUNK(c, stg) do {                                              \
    const int kk = (c) * BK;                                                 \
    unsigned base = sb + (stg) * STAGE_B;                                    \
    cp_async16(base + s0,          A + gA0 + kk);                            \
    cp_async16(base + s1,          A + gA1 + kk);                            \
    cp_async16(base + TILE_B + s0, B + gB0 + kk);                            \
    cp_async16(base + TILE_B + s1, B + gB1 + kk);                            \
} while (0)

    float acc[2][4][4];
#pragma unroll
    for (int i = 0; i < 2; i++)
#pragma unroll
        for (int j = 0; j < 4; j++)
#pragma unroll
            for (int q = 0; q < 4; q++) acc[i][j][q] = 0.0f;

    const int l7 = lane & 7, m4 = lane >> 3;
    const unsigned aoff = (wm * 32 + (m4 & 1) * 8 + l7) * ROW_BYTES + (m4 >> 1) * 16;
    const unsigned boff = (wn * 32 + ((m4 & 2) ? 8 : 0) + l7) * ROW_BYTES + (m4 & 1) * 16;

    const int NCH = K / BK;   // 16

    LOAD_CHUNK(0, 0); CP_COMMIT();
    LOAD_CHUNK(1, 1); CP_COMMIT();

    for (int c = 0; c < NCH; c++) {
        cp_wait<1>();
        __syncthreads();

        if (c + 2 < NCH) LOAD_CHUNK(c + 2, (c + 2) % NSTAGE);
        CP_COMMIT();

        const unsigned stg = sb + (c % NSTAGE) * STAGE_B;
#pragma unroll
        for (int ks = 0; ks < 4; ks++) {
            const unsigned kb = ks * 32;
            unsigned ah[2][4], bh[2][4];
#pragma unroll
            for (int mi = 0; mi < 2; mi++)
                ldm_x4(stg + aoff + mi * (16 * ROW_BYTES) + kb, ah[mi]);
#pragma unroll
            for (int ng = 0; ng < 2; ng++)
                ldm_x4(stg + TILE_B + boff + ng * (16 * ROW_BYTES) + kb, bh[ng]);
#pragma unroll
            for (int mi = 0; mi < 2; mi++)
#pragma unroll
                for (int ni = 0; ni < 4; ni++) {
                    const int ng = ni >> 1, half = (ni & 1) * 2;
                    unsigned br[2] = { bh[ng][half], bh[ng][half + 1] };
                    mma_f16(acc[mi][ni], ah[mi], br);
                }
        }
    }

    const int erow = row0 + wm * 32 + (lane >> 2);
    const int ecol = col0 + wn * 32 + (lane & 3) * 2;
#pragma unroll
    for (int mi = 0; mi < 2; mi++)
#pragma unroll
        for (int ni = 0; ni < 4; ni++) {
            const size_t o0 = (size_t)(erow + mi * 16) * N + ecol + ni * 8;
            const size_t o1 = o0 + (size_t)8 * N;
            if (MODE == 0) {
                C[o0] = acc[mi][ni][0]; C[o0 + 1] = acc[mi][ni][1];
                C[o1] = acc[mi][ni][2]; C[o1 + 1] = acc[mi][ni][3];
            } else {
                *(unsigned*)(Ch + o0) = pkh2(acc[mi][ni][0], acc[mi][ni][1]);
                *(unsigned*)(Ch + o1) = pkh2(acc[mi][ni][2], acc[mi][ni][3]);
            }
        }
#undef LOAD_CHUNK
}

__global__ __launch_bounds__(GT) void gemm_mma(
    const __half* __restrict__ A, const __half* __restrict__ B,
    float* __restrict__ C, int M, int N, int K)
{
    gemm_body<0>(A, B, C, nullptr, M, N, K, blockIdx.y * 128, blockIdx.x * 128);
}

// Fused QKV: z=0 -> q fp32, z=1 -> k fp32, z=2 -> v fp16.
__global__ __launch_bounds__(GT) void gemm_qkv(
    const __half* __restrict__ A, const __half* __restrict__ W,
    float* __restrict__ Cq, float* __restrict__ Ck, __half* __restrict__ Vh)
{
    const size_t WSZ = (size_t)DIMM * DIMM;
    const int z = blockIdx.z;
    const __half* B = W + (size_t)z * WSZ;
    if (z == 2) {
        gemm_body<1>(A, B, nullptr, Vh, BS, DIMM, DIMM,
                     blockIdx.y * 128, blockIdx.x * 128);
    } else {
        float* C = (z == 0) ? Cq : Ck;
        gemm_body<0>(A, B, C, nullptr, BS, DIMM, DIMM,
                     blockIdx.y * 128, blockIdx.x * 128);
    }
}

// ---------------------------------------------------------------------------
// RoPE: reads fp32 q/k, writes fp16 directly.
// ---------------------------------------------------------------------------
#define ROT(xx, yy, c, s) { float _t = (xx)*(c) - (yy)*(s); (yy) = (xx)*(s) + (yy)*(c); (xx) = _t; }

__global__ __launch_bounds__(256) void rope_cvt(const float* __restrict__ q,
                                                const float* __restrict__ k,
                                                const int* __restrict__ Hm,
                                                const int* __restrict__ Bm,
                                                const float* __restrict__ fc,
                                                const float* __restrict__ fs,
                                                __half* __restrict__ qh,
                                                __half* __restrict__ kh)
{
    const int tok = blockIdx.x;
    const int tid = threadIdx.x;
    const int h = tid >> 4;
    const int m = tid & 15;
    const int base = tok * DIMM + h * HD;

    float2 qab = *(const float2*)&q[base + 2 * m];
    float2 qcd = *(const float2*)&q[base + 2 * m + 32];
    float2 kab = *(const float2*)&k[base + 2 * m];
    float2 kcd = *(const float2*)&k[base + 2 * m + 32];

    const float cH0 = fc[32 + m],      sH0 = fs[32 + m];
    const float cH1 = fc[32 + m + 16], sH1 = fs[32 + m + 16];
    const float cB0a = fc[32 + 2 * m],     sB0a = fs[32 + 2 * m];
    const float cB0b = fc[32 + 2 * m + 1], sB0b = fs[32 + 2 * m + 1];
    const float cB1a = fc[64 + 2 * m],     sB1a = fs[64 + 2 * m];
    const float cB1b = fc[64 + 2 * m + 1], sB1b = fs[64 + 2 * m + 1];

#pragma unroll
    for (int i = 0; i < 6; i++) {
        if (Hm[i * BS + tok]) {
            ROT(qab.x, qab.y, cH0, sH0); ROT(qcd.x, qcd.y, cH1, sH1);
            ROT(kab.x, kab.y, cH0, sH0); ROT(kcd.x, kcd.y, cH1, sH1);
        }
        if (Bm[(i * 2 + 0) * BS + tok]) {
            ROT(qab.x, qcd.x, cB0a, sB0a); ROT(qab.y, qcd.y, cB0b, sB0b);
            ROT(kab.x, kcd.x, cB0a, sB0a); ROT(kab.y, kcd.y, cB0b, sB0b);
        }
        if (Bm[(i * 2 + 1) * BS + tok]) {
            ROT(qab.x, qcd.x, cB1a, sB1a); ROT(qab.y, qcd.y, cB1b, sB1b);
            ROT(kab.x, kcd.x, cB1a, sB1a); ROT(kab.y, kcd.y, cB1b, sB1b);
        }
    }

    *(unsigned*)(qh + base + 2 * m)      = pkh2(qab.x, qab.y);
    *(unsigned*)(qh + base + 2 * m + 32) = pkh2(qcd.x, qcd.y);
    *(unsigned*)(kh + base + 2 * m)      = pkh2(kab.x, kab.y);
    *(unsigned*)(kh + base + 2 * m + 32) = pkh2(kcd.x, kcd.y);
}

// ---------------------------------------------------------------------------
// Flash attention (R12 q128/kv128 structure, single-pass fp16).
// ---------------------------------------------------------------------------
#define FROWB  144
#define FTILE  (128 * FROWB)            // 18432 per plane
#define FSTAGE (2 * FTILE)              // K, V
#define FLASH_SMEM (FTILE + 2 * FSTAGE) // 92160

__global__ __launch_bounds__(256, 1) void flash_mma(
    const __half* __restrict__ qh, const __half* __restrict__ kh,
    const __half* __restrict__ vh, const int* __restrict__ masks,
    __half* __restrict__ aoh)
{
    extern __shared__ char smem[];
    const unsigned sb = smem_u32(smem);
    const int tid = threadIdx.x, lane = tid & 31, wid = tid >> 5;
    const int bh = blockIdx.y, b = bh >> 4, h = bh & 15;
    const int q0 = blockIdx.x * 128;
    const int wq0 = wid * 16;

    const unsigned sQ = sb;
    const unsigned sKV = sb + FTILE;

#pragma unroll
    for (int t = 0; t < 4; t++) {
        int seg = tid + t * 256, row = seg >> 3, s = seg & 7;
        size_t g = (size_t)(b * SS + q0 + row) * DIMM + h * HD + s * 8;
        cp_async16(sQ + row * FROWB + s * 16, qh + g);
    }

#define KV_LOAD(kt, stg) do {                                                \
    unsigned base = sKV + (stg) * FSTAGE;                                    \
    _Pragma("unroll")                                                        \
    for (int t = 0; t < 4; t++) {                                            \
        int seg = tid + t * 256, row = seg >> 3, s = seg & 7;                \
        size_t g = (size_t)(b * SS + (kt) * 128 + row) * DIMM + h * HD + s * 8; \
        unsigned sa = row * FROWB + s * 16;                                  \
        cp_async16(base + sa,         kh + g);                               \
        cp_async16(base + FTILE + sa, vh + g);                               \
    }                                                                        \
} while (0)

    KV_LOAD(0, 0); CP_COMMIT();
    KV_LOAD(1, 1); CP_COMMIT();

    float m0 = -1e30f, m1 = -1e30f, l0 = 0.0f, l1 = 0.0f;
    float acc_o[8][4];
#pragma unroll
    for (int j = 0; j < 8; j++)
#pragma unroll
        for (int q = 0; q < 4; q++) acc_o[j][q] = 0.0f;

    const int l7 = lane & 7, m4 = lane >> 3;
    const unsigned qoff = (wq0 + (m4 & 1) * 8 + l7) * FROWB + (m4 >> 1) * 16;
    const unsigned koff = (((m4 & 2) ? 8 : 0) + l7) * FROWB + (m4 & 1) * 16;
    const unsigned voff = (lane & 15) * FROWB + (lane >> 4) * 16;

    const int gr0 = q0 + wq0 + (lane >> 2);
    const int* mrow0 = masks + (size_t)b * SS * SS + (size_t)gr0 * SS;
    const int* mrow1 = mrow0 + 8 * SS;

    for (int kt = 0; kt < 8; kt++) {
        if (kt == 7) cp_wait<0>(); else cp_wait<1>();
        __syncthreads();
        const unsigned kbase = sKV + (kt & 1) * FSTAGE;

        float s[16][4];
#pragma unroll
        for (int ni = 0; ni < 16; ni++)
#pragma unroll
            for (int q = 0; q < 4; q++) s[ni][q] = 0.0f;

#pragma unroll
        for (int ks = 0; ks < 4; ks++) {
            unsigned ah[4];
            ldm_x4(sQ + qoff + ks * 32, ah);
#pragma unroll
            for (int g = 0; g < 8; g++) {
                unsigned bh4[4];
                ldm_x4(kbase + koff + g * (16 * FROWB) + ks * 32, bh4);
                unsigned b0[2] = { bh4[0], bh4[1] }, b1[2] = { bh4[2], bh4[3] };
                mma_f16(s[2 * g],     ah, b0);
                mma_f16(s[2 * g + 1], ah, b1);
            }
        }

        const int kc0 = kt * 128 + (lane & 3) * 2;
#pragma unroll
        for (int ni = 0; ni < 16; ni++) {
            int2 mk0 = *(const int2*)(mrow0 + kc0 + ni * 8);
            int2 mk1 = *(const int2*)(mrow1 + kc0 + ni * 8);
            s[ni][0] = mk0.x ? s[ni][0] * 0.125f : NEG_INF_F;
            s[ni][1] = mk0.y ? s[ni][1] * 0.125f : NEG_INF_F;
            s[ni][2] = mk1.x ? s[ni][2] * 0.125f : NEG_INF_F;
            s[ni][3] = mk1.y ? s[ni][3] * 0.125f : NEG_INF_F;
        }

        float mx0 = -1e30f, mx1 = -1e30f;
#pragma unroll
        for (int ni = 0; ni < 16; ni++) {
            mx0 = fmaxf(mx0, fmaxf(s[ni][0], s[ni][1]));
            mx1 = fmaxf(mx1, fmaxf(s[ni][2], s[ni][3]));
        }
        mx0 = fmaxf(mx0, __shfl_xor_sync(0xffffffffu, mx0, 1));
        mx0 = fmaxf(mx0, __shfl_xor_sync(0xffffffffu, mx0, 2));
        mx1 = fmaxf(mx1, __shfl_xor_sync(0xffffffffu, mx1, 1));
        mx1 = fmaxf(mx1, __shfl_xor_sync(0xffffffffu, mx1, 2));

        float mn0 = fmaxf(m0, mx0), mn1 = fmaxf(m1, mx1);
        float al0 = __expf(m0 - mn0), al1 = __expf(m1 - mn1);
        m0 = mn0; m1 = mn1;

        float sum0 = 0.0f, sum1 = 0.0f;
#pragma unroll
        for (int ni = 0; ni < 16; ni++) {
            s[ni][0] = __expf(s[ni][0] - mn0);
            s[ni][1] = __expf(s[ni][1] - mn0);
            s[ni][2] = __expf(s[ni][2] - mn1);
            s[ni][3] = __expf(s[ni][3] - mn1);
            sum0 += s[ni][0] + s[ni][1];
            sum1 += s[ni][2] + s[ni][3];
        }
        l0 = l0 * al0 + sum0;
        l1 = l1 * al1 + sum1;

#pragma unroll
        for (int j = 0; j < 8; j++) {
            acc_o[j][0] *= al0; acc_o[j][1] *= al0;
            acc_o[j][2] *= al1; acc_o[j][3] *= al1;
        }

#pragma unroll
        for (int kc = 0; kc < 8; kc++) {
            unsigned aP[4];
            aP[0] = pkh2(s[2 * kc][0],     s[2 * kc][1]);
            aP[1] = pkh2(s[2 * kc][2],     s[2 * kc][3]);
            aP[2] = pkh2(s[2 * kc + 1][0], s[2 * kc + 1][1]);
            aP[3] = pkh2(s[2 * kc + 1][2], s[2 * kc + 1][3]);
#pragma unroll
            for (int dg = 0; dg < 4; dg++) {
                unsigned bv[4];
                ldm_x4_t(kbase + FTILE + voff + kc * (16 * FROWB) + dg * 32, bv);
                unsigned b0[2] = { bv[0], bv[1] }, b1[2] = { bv[2], bv[3] };
                mma_f16(acc_o[2 * dg],     aP, b0);
                mma_f16(acc_o[2 * dg + 1], aP, b1);
            }
        }

        __syncthreads();
        if (kt + 2 < 8) { KV_LOAD(kt + 2, kt & 1); CP_COMMIT(); }
    }

    // quad reduction of l, then normalize + store fp16
    l0 += __shfl_xor_sync(0xffffffffu, l0, 1);
    l0 += __shfl_xor_sync(0xffffffffu, l0, 2);
    l1 += __shfl_xor_sync(0xffffffffu, l1, 1);
    l1 += __shfl_xor_sync(0xffffffffu, l1, 2);
    const float inv0 = 1.0f / l0, inv1 = 1.0f / l1;
    const size_t o0 = (size_t)(b * SS + gr0) * DIMM + h * HD + (lane & 3) * 2;
    const size_t o1 = o0 + (size_t)8 * DIMM;
#pragma unroll
    for (int j = 0; j < 8; j++) {
        *(unsigned*)(aoh + o0 + j * 8) = pkh2(acc_o[j][0] * inv0, acc_o[j][1] * inv0);
        *(unsigned*)(aoh + o1 + j * 8) = pkh2(acc_o[j][2] * inv1, acc_o[j][3] * inv1);
    }
#undef KV_LOAD
}

// ---------------------------------------------------------------------------
extern "C" void kernel_launch(void* const* d_in, const int* in_sizes, int n_in,
                              void* d_out, int out_size)
{
    const float* x     = (const float*)d_in[0];
    const int*   masks = (const int*)d_in[1];
    const int*   Hm    = (const int*)d_in[2];
    const int*   Bm    = (const int*)d_in[3];
    const float* fc    = (const float*)d_in[4];
    const float* fs    = (const float*)d_in[5];
    const float* wq    = (const float*)d_in[6];
    const float* wk    = (const float*)d_in[7];
    const float* wv    = (const float*)d_in[8];
    const float* wo    = (const float*)d_in[9];
    float* out = (float*)d_out;

    float *gq, *gk;
    __half *xh, *aoh, *wh, *qh, *kh, *vh;
    cudaGetSymbolAddress((void**)&gq,  g_q);
    cudaGetSymbolAddress((void**)&gk,  g_k);
    cudaGetSymbolAddress((void**)&xh,  g_xh);
    cudaGetSymbolAddress((void**)&aoh, g_aoh);
    cudaGetSymbolAddress((void**)&wh,  g_wh);
    cudaGetSymbolAddress((void**)&qh,  g_qh);
    cudaGetSymbolAddress((void**)&kh,  g_kh);
    cudaGetSymbolAddress((void**)&vh,  g_vh);

    static bool attr_done = false;
    if (!attr_done) {
        cudaFuncSetAttribute(gemm_mma,  cudaFuncAttributeMaxDynamicSharedMemorySize, GEMM_SMEM);
        cudaFuncSetAttribute(gemm_qkv,  cudaFuncAttributeMaxDynamicSharedMemorySize, GEMM_SMEM);
        cudaFuncSetAttribute(flash_mma, cudaFuncAttributeMaxDynamicSharedMemorySize, FLASH_SMEM);
        attr_done = true;
    }

    prep_w4<<<dim3(32, 32, 4), 256>>>(wq, wk, wv, wo, wh);

    cvt_f32<<<BS * DIMM / 4 / 256, 256>>>((const float4*)x, xh);

    gemm_qkv<<<dim3(DIMM / 128, BS / 128, 3), GT, GEMM_SMEM>>>(
        xh, wh, gq, gk, vh);

    rope_cvt<<<BS, 256>>>(gq, gk, Hm, Bm, fc, fs, qh, kh);

    flash_mma<<<dim3(SS / 128, BB * NH), 256, FLASH_SMEM>>>(
        qh, kh, vh, masks, aoh);

    gemm_mma<<<dim3(DIMM / 128, BS / 128), GT, GEMM_SMEM>>>(
        aoh, wh + 3 * (size_t)DIMM * DIMM, out, BS, DIMM, DIMM);
}